// round 1
// baseline (speedup 1.0000x reference)
#include <cuda_runtime.h>
#include <math.h>

#define BATCH 2
#define TLEN 2048
#define DIM 1024
#define HEADS 16
#define DH 64
#define WINDOW 32
#define NTOK (BATCH * TLEN)
#define LN_EPS 1e-5f

// ---------------- scratch (device globals; no allocations) ----------------
__device__ float g_h[(size_t)NTOK * DIM];          // LN output, [tok, DIM]
__device__ float g_qkv[(size_t)NTOK * 3 * DIM];    // [tok, 3*DIM]
__device__ float g_att[(size_t)NTOK * DIM];        // attention output, [tok, DIM]
__device__ float g_proj[(size_t)NTOK * DIM];       // out-proj, [tok, DIM]

// ---------------- 1) LayerNorm + transpose [B,C,T] -> [tok,C] -------------
// grid (T/32, B), block (32, 8). threadIdx.x indexes t (coalesced on x).
__global__ void ln_transpose_kernel(const float* __restrict__ x,
                                    const float* __restrict__ w,
                                    const float* __restrict__ bias) {
    const int b  = blockIdx.y;
    const int t0 = blockIdx.x * 32;
    const int tx = threadIdx.x, ty = threadIdx.y;
    const float* xb = x + (size_t)b * DIM * TLEN;

    float s = 0.f, ss = 0.f;
    for (int c = ty; c < DIM; c += 8) {
        float v = xb[(size_t)c * TLEN + t0 + tx];
        s += v; ss += v * v;
    }
    __shared__ float rs[8][32], rq[8][32];
    rs[ty][tx] = s; rq[ty][tx] = ss;
    __syncthreads();
    __shared__ float mu[32], rstd[32];
    if (ty == 0) {
        float a = 0.f, q = 0.f;
        #pragma unroll
        for (int i = 0; i < 8; i++) { a += rs[i][tx]; q += rq[i][tx]; }
        float m   = a / (float)DIM;
        float var = q / (float)DIM - m * m;
        mu[tx]   = m;
        rstd[tx] = rsqrtf(var + LN_EPS);
    }
    __syncthreads();

    __shared__ float tile[32][33];
    for (int c0 = 0; c0 < DIM; c0 += 32) {
        #pragma unroll
        for (int k = 0; k < 4; k++) {
            int cl = ty + 8 * k;
            tile[cl][tx] = xb[(size_t)(c0 + cl) * TLEN + t0 + tx];
        }
        __syncthreads();
        #pragma unroll
        for (int k = 0; k < 4; k++) {
            int tl = ty + 8 * k;
            int c  = c0 + tx;
            float v = (tile[tx][tl] - mu[tl]) * rstd[tl] * w[c] + bias[c];
            g_h[((size_t)b * TLEN + t0 + tl) * DIM + c] = v;
        }
        __syncthreads();
    }
}

// ---------------- 2/5) SGEMM 128x128x8, 8x8 per thread --------------------
// which==0: A=g_h   (K=1024), C=g_qkv (N=3*DIM)
// which==1: A=g_att (K=1024), C=g_proj (N=DIM)
__global__ __launch_bounds__(256, 2)
void sgemm_kernel(int which, const float* __restrict__ Bm, int M, int N, int K) {
    const float* A = (which == 0) ? g_h : g_att;
    float*       C = (which == 0) ? g_qkv : g_proj;

    __shared__ float As[8][128];
    __shared__ float Bs[8][128];

    const int tid = threadIdx.x;
    const int tx = tid & 15, ty = tid >> 4;
    const int m0 = blockIdx.y * 128, n0 = blockIdx.x * 128;

    const int arow = tid >> 1;           // 0..127
    const int acol = (tid & 1) * 4;      // 0 or 4
    const int brow = tid >> 5;           // 0..7
    const int bcol = (tid & 31) * 4;     // 0..124

    float acc[8][8];
    #pragma unroll
    for (int i = 0; i < 8; i++)
        #pragma unroll
        for (int j = 0; j < 8; j++) acc[i][j] = 0.f;

    for (int k0 = 0; k0 < K; k0 += 8) {
        float4 a = *(const float4*)&A[(size_t)(m0 + arow) * K + k0 + acol];
        As[acol + 0][arow] = a.x;
        As[acol + 1][arow] = a.y;
        As[acol + 2][arow] = a.z;
        As[acol + 3][arow] = a.w;
        float4 bvec = *(const float4*)&Bm[(size_t)(k0 + brow) * N + n0 + bcol];
        *(float4*)&Bs[brow][bcol] = bvec;
        __syncthreads();

        #pragma unroll
        for (int k = 0; k < 8; k++) {
            float ar[8], br[8];
            #pragma unroll
            for (int i = 0; i < 8; i++) ar[i] = As[k][ty * 8 + i];
            #pragma unroll
            for (int j = 0; j < 8; j++) br[j] = Bs[k][tx * 8 + j];
            #pragma unroll
            for (int i = 0; i < 8; i++)
                #pragma unroll
                for (int j = 0; j < 8; j++) acc[i][j] = fmaf(ar[i], br[j], acc[i][j]);
        }
        __syncthreads();
    }

    #pragma unroll
    for (int i = 0; i < 8; i++) {
        #pragma unroll
        for (int j = 0; j < 8; j += 4) {
            float4 v = make_float4(acc[i][j], acc[i][j+1], acc[i][j+2], acc[i][j+3]);
            *(float4*)&C[(size_t)(m0 + ty * 8 + i) * N + n0 + tx * 8 + j] = v;
        }
    }
}

// ---------------- 3) RoPE in-place on q,k sections of g_qkv ---------------
__global__ void rope_kernel() {
    int idx = blockIdx.x * blockDim.x + threadIdx.x;   // NTOK*2*16*32 threads
    if (idx >= NTOK * 1024) return;
    int d     = idx & 31;
    int h     = (idx >> 5) & 15;
    int sec   = (idx >> 9) & 1;        // 0=q, 1=k
    int token = idx >> 10;
    int t     = token % TLEN;

    // inv_freq = 10000^(-d/32)
    float inv = expf(-(float)d * (9.210340371976184f / 32.0f));
    float f   = (float)t * inv;
    float c = cosf(f), s = sinf(f);

    size_t base = (size_t)token * (3 * DIM) + sec * DIM + h * DH + d;
    float v1 = g_qkv[base];
    float v2 = g_qkv[base + 32];
    g_qkv[base]      = v1 * c - v2 * s;
    g_qkv[base + 32] = v2 * c + v1 * s;
}

// ---------------- 4) windowed causal attention -----------------------------
// grid (T/32, B*HEADS), block 256 (8 warps, 4 queries per warp).
__global__ __launch_bounds__(256)
void attn_kernel() {
    const int t0 = blockIdx.x * 32;
    const int bh = blockIdx.y;
    const int b = bh / HEADS, h = bh % HEADS;

    __shared__ float Qs[32][64];
    __shared__ float Ks[64][65];
    __shared__ float Vs[64][65];

    const int tid = threadIdx.x;

    // load Q tile: 32 queries x 64 dims
    for (int i = tid; i < 32 * 64; i += 256) {
        int q = i >> 6, d = i & 63;
        Qs[q][d] = g_qkv[((size_t)(b * TLEN + t0 + q)) * (3 * DIM) + h * DH + d];
    }
    // load K/V window rows: kpos = t0-31 .. t0+31  (63 rows)
    for (int i = tid; i < 63 * 64; i += 256) {
        int r = i >> 6, d = i & 63;
        int kpos = t0 - 31 + r;
        float kv = 0.f, vv = 0.f;
        if (kpos >= 0) {
            size_t off = ((size_t)(b * TLEN + kpos)) * (3 * DIM) + h * DH + d;
            kv = g_qkv[off + DIM];
            vv = g_qkv[off + 2 * DIM];
        }
        Ks[r][d] = kv;
        Vs[r][d] = vv;
    }
    __syncthreads();

    const int warp = tid >> 5, lane = tid & 31;
    #pragma unroll
    for (int j = 0; j < 4; j++) {
        const int ql   = warp * 4 + j;       // 0..31
        const int qpos = t0 + ql;
        const int r    = ql + lane;          // smem key row (0..62)
        const int kpos = qpos - 31 + lane;
        const bool valid = (kpos >= 0);

        float s = 0.f;
        #pragma unroll
        for (int d = 0; d < 64; d++) s = fmaf(Qs[ql][d], Ks[r][d], s);
        s *= 0.125f;                          // 1/sqrt(64)
        s = valid ? s : -INFINITY;

        float m = s;
        #pragma unroll
        for (int o = 16; o; o >>= 1) m = fmaxf(m, __shfl_xor_sync(0xffffffffu, m, o));
        float p = valid ? expf(s - m) : 0.f;
        float sum = p;
        #pragma unroll
        for (int o = 16; o; o >>= 1) sum += __shfl_xor_sync(0xffffffffu, sum, o);
        p /= sum;

        float o0 = 0.f, o1 = 0.f;
        #pragma unroll
        for (int jj = 0; jj < 32; jj++) {
            float pj = __shfl_sync(0xffffffffu, p, jj);
            int rj = ql + jj;
            o0 = fmaf(pj, Vs[rj][2 * lane],     o0);
            o1 = fmaf(pj, Vs[rj][2 * lane + 1], o1);
        }
        size_t oo = ((size_t)(b * TLEN + qpos)) * DIM + h * DH + 2 * lane;
        g_att[oo]     = o0;
        g_att[oo + 1] = o1;
    }
}

// ---------------- 6) transpose + residual: out[b,c,t] = proj[tok,c] + x ---
// grid (T/32, DIM/32, B), block (32,8)
__global__ void add_transpose_kernel(const float* __restrict__ x,
                                     float* __restrict__ out) {
    const int b  = blockIdx.z;
    const int t0 = blockIdx.x * 32, c0 = blockIdx.y * 32;
    const int tx = threadIdx.x, ty = threadIdx.y;
    __shared__ float tile[32][33];
    #pragma unroll
    for (int k = 0; k < 4; k++) {
        int tl = ty + 8 * k;
        tile[tl][tx] = g_proj[((size_t)(b * TLEN + t0 + tl)) * DIM + c0 + tx];
    }
    __syncthreads();
    #pragma unroll
    for (int k = 0; k < 4; k++) {
        int cl = ty + 8 * k;
        size_t idx = ((size_t)b * DIM + c0 + cl) * TLEN + t0 + tx;
        out[idx] = tile[tx][cl] + x[idx];
    }
}

// ---------------- launch ---------------------------------------------------
extern "C" void kernel_launch(void* const* d_in, const int* in_sizes, int n_in,
                              void* d_out, int out_size) {
    const float* x     = (const float*)d_in[0];
    const float* ln_w  = (const float*)d_in[1];
    const float* ln_b  = (const float*)d_in[2];
    const float* w_qkv = (const float*)d_in[3];
    const float* w_out = (const float*)d_in[4];
    float* out = (float*)d_out;

    // 1) LayerNorm + transpose to [tok, DIM]
    ln_transpose_kernel<<<dim3(TLEN / 32, BATCH), dim3(32, 8)>>>(x, ln_w, ln_b);

    // 2) QKV GEMM: [4096,1024] x [1024,3072] -> g_qkv
    sgemm_kernel<<<dim3((3 * DIM) / 128, NTOK / 128), 256>>>(0, w_qkv, NTOK, 3 * DIM, DIM);

    // 3) RoPE on q,k
    {
        int total = NTOK * 1024;
        rope_kernel<<<(total + 255) / 256, 256>>>();
    }

    // 4) windowed attention
    attn_kernel<<<dim3(TLEN / 32, BATCH * HEADS), 256>>>();

    // 5) output projection: [4096,1024] x [1024,1024] -> g_proj
    sgemm_kernel<<<dim3(DIM / 128, NTOK / 128), 256>>>(1, w_out, NTOK, DIM, DIM);

    // 6) transpose + residual
    add_transpose_kernel<<<dim3(TLEN / 32, DIM / 32, BATCH), dim3(32, 8)>>>(x, out);
}

// round 8
// speedup vs baseline: 1.7391x; 1.7391x over previous
#include <cuda_runtime.h>
#include <cuda_bf16.h>
#include <cstdint>
#include <math.h>

#define BATCH 2
#define TLEN 2048
#define DIM 1024
#define HEADS 16
#define DH 64
#define WINDOW 32
#define NTOK (BATCH * TLEN)
#define LN_EPS 1e-5f

// ---------------- scratch (device globals; same 96 MB set as passing R1) --
__device__ float g_h[(size_t)NTOK * DIM];          // LN output, [tok, DIM]
__device__ float g_qkv[(size_t)NTOK * 3 * DIM];    // [tok, 3*DIM]
__device__ float g_att[(size_t)NTOK * DIM];        // attention output, [tok, DIM]
__device__ float g_proj[(size_t)NTOK * DIM];       // out-proj, [tok, DIM]

// ---------------- 1) LayerNorm + transpose [B,C,T] -> [tok,C] -------------
// (identical to R1)
__global__ void ln_transpose_kernel(const float* __restrict__ x,
                                    const float* __restrict__ w,
                                    const float* __restrict__ bias) {
    const int b  = blockIdx.y;
    const int t0 = blockIdx.x * 32;
    const int tx = threadIdx.x, ty = threadIdx.y;
    const float* xb = x + (size_t)b * DIM * TLEN;

    float s = 0.f, ss = 0.f;
    for (int c = ty; c < DIM; c += 8) {
        float v = xb[(size_t)c * TLEN + t0 + tx];
        s += v; ss += v * v;
    }
    __shared__ float rs[8][32], rq[8][32];
    rs[ty][tx] = s; rq[ty][tx] = ss;
    __syncthreads();
    __shared__ float mu[32], rstd[32];
    if (ty == 0) {
        float a = 0.f, q = 0.f;
        #pragma unroll
        for (int i = 0; i < 8; i++) { a += rs[i][tx]; q += rq[i][tx]; }
        float m   = a / (float)DIM;
        float var = q / (float)DIM - m * m;
        mu[tx]   = m;
        rstd[tx] = rsqrtf(var + LN_EPS);
    }
    __syncthreads();

    __shared__ float tile[32][33];
    for (int c0 = 0; c0 < DIM; c0 += 32) {
        #pragma unroll
        for (int k = 0; k < 4; k++) {
            int cl = ty + 8 * k;
            tile[cl][tx] = xb[(size_t)(c0 + cl) * TLEN + t0 + tx];
        }
        __syncthreads();
        #pragma unroll
        for (int k = 0; k < 4; k++) {
            int tl = ty + 8 * k;
            int c  = c0 + tx;
            float v = (tile[tx][tl] - mu[tl]) * rstd[tl] * w[c] + bias[c];
            g_h[((size_t)b * TLEN + t0 + tl) * DIM + c] = v;
        }
        __syncthreads();
    }
}

// ---------------- 2/5) bf16x3 tensor-core GEMM, in-register split ---------
// C[M,N] = A[M,K] * B[K,N], all fp32 in global (R1 layout, no pre-split).
// CTA tile 128x64xk16, 8 warps (4m x 2n), warp tile 32x32 (32 acc regs).
// fp32 smem tiles; fragments converted to bf16 hi/lo in registers.
#define ASTRIDE 20   // fp32 A row stride in smem (128 rows x 16 cols)
#define BSTRIDE 68   // fp32 B row stride in smem (16 rows x 64 cols)

#define MMA16816(d, a0, a1, a2, a3, b0, b1)                                   \
    asm volatile("mma.sync.aligned.m16n8k16.row.col.f32.bf16.bf16.f32 "      \
                 "{%0,%1,%2,%3}, {%4,%5,%6,%7}, {%8,%9}, {%0,%1,%2,%3};"     \
                 : "+f"(d[0]), "+f"(d[1]), "+f"(d[2]), "+f"(d[3])             \
                 : "r"(a0), "r"(a1), "r"(a2), "r"(a3), "r"(b0), "r"(b1))

__device__ __forceinline__ void split2(float fx, float fy,
                                       uint32_t& hi, uint32_t& lo) {
    __nv_bfloat162 h = __floats2bfloat162_rn(fx, fy);
    float2 hf = __bfloat1622float2(h);
    __nv_bfloat162 l = __floats2bfloat162_rn(fx - hf.x, fy - hf.y);
    hi = *(uint32_t*)&h;
    lo = *(uint32_t*)&l;
}

__global__ __launch_bounds__(256)
void sgemm_tc_kernel(int which, const float* __restrict__ Bm, int N) {
    const float* __restrict__ A = (which == 0) ? g_h : g_att;
    float* __restrict__ C = (which == 0) ? g_qkv : g_proj;
    const int K = DIM;

    __shared__ float sA[128 * ASTRIDE];   // 10240 B
    __shared__ float sB[16 * BSTRIDE];    // 4352 B

    const int tid  = threadIdx.x;
    const int warp = tid >> 5, lane = tid & 31;
    const int wm0 = (warp & 3) * 32;
    const int wn0 = (warp >> 2) * 32;
    const int m0 = blockIdx.y * 128;
    const int n0 = blockIdx.x * 64;

    float acc[2][4][4];
    #pragma unroll
    for (int i = 0; i < 2; i++)
        #pragma unroll
        for (int j = 0; j < 4; j++)
            #pragma unroll
            for (int k = 0; k < 4; k++) acc[i][j][k] = 0.f;

    const int r  = lane >> 2;
    const int c2 = (lane & 3) * 2;

    for (int kt = 0; kt < K / 16; kt++) {
        const int kbase = kt * 16;
        // load A: 128 rows x 16 cols fp32 = 512 float4, 2 per thread
        #pragma unroll
        for (int i = 0; i < 2; i++) {
            int lin = tid + i * 256;
            int row = lin >> 2;
            int col = (lin & 3) * 4;
            *(float4*)&sA[row * ASTRIDE + col] =
                *(const float4*)&A[(size_t)(m0 + row) * K + kbase + col];
        }
        // load B: 16 rows x 64 cols fp32 = 256 float4, 1 per thread
        {
            int row = tid >> 4;
            int col = (tid & 15) * 4;
            *(float4*)&sB[row * BSTRIDE + col] =
                *(const float4*)&Bm[(size_t)(kbase + row) * N + n0 + col];
        }
        __syncthreads();

        // B fragments: bf16 hi/lo from fp32 smem
        uint32_t bh[4][2], bl[4][2];
        #pragma unroll
        for (int nt = 0; nt < 4; nt++) {
            int n = wn0 + nt * 8 + r;
            split2(sB[c2 * BSTRIDE + n],       sB[(c2 + 1) * BSTRIDE + n],
                   bh[nt][0], bl[nt][0]);
            split2(sB[(c2 + 8) * BSTRIDE + n], sB[(c2 + 9) * BSTRIDE + n],
                   bh[nt][1], bl[nt][1]);
        }
        #pragma unroll
        for (int mt = 0; mt < 2; mt++) {
            int row = wm0 + mt * 16 + r;
            float2 f0 = *(const float2*)&sA[row * ASTRIDE + c2];
            float2 f1 = *(const float2*)&sA[(row + 8) * ASTRIDE + c2];
            float2 f2 = *(const float2*)&sA[row * ASTRIDE + c2 + 8];
            float2 f3 = *(const float2*)&sA[(row + 8) * ASTRIDE + c2 + 8];
            uint32_t ah0, ah1, ah2, ah3, al0, al1, al2, al3;
            split2(f0.x, f0.y, ah0, al0);
            split2(f1.x, f1.y, ah1, al1);
            split2(f2.x, f2.y, ah2, al2);
            split2(f3.x, f3.y, ah3, al3);
            #pragma unroll
            for (int nt = 0; nt < 4; nt++) {
                MMA16816(acc[mt][nt], ah0, ah1, ah2, ah3, bh[nt][0], bh[nt][1]);
                MMA16816(acc[mt][nt], ah0, ah1, ah2, ah3, bl[nt][0], bl[nt][1]);
                MMA16816(acc[mt][nt], al0, al1, al2, al3, bh[nt][0], bh[nt][1]);
            }
        }
        __syncthreads();
    }

    #pragma unroll
    for (int mt = 0; mt < 2; mt++)
        #pragma unroll
        for (int nt = 0; nt < 4; nt++) {
            int row = m0 + wm0 + mt * 16 + r;
            int col = n0 + wn0 + nt * 8 + c2;
            float2 v0 = make_float2(acc[mt][nt][0], acc[mt][nt][1]);
            float2 v1 = make_float2(acc[mt][nt][2], acc[mt][nt][3]);
            *(float2*)&C[(size_t)row * N + col]       = v0;
            *(float2*)&C[(size_t)(row + 8) * N + col] = v1;
        }
}

// ---------------- 3) RoPE in-place on q,k sections of g_qkv ---------------
// (identical to R1)
__global__ void rope_kernel() {
    int idx = blockIdx.x * blockDim.x + threadIdx.x;
    if (idx >= NTOK * 1024) return;
    int d     = idx & 31;
    int h     = (idx >> 5) & 15;
    int sec   = (idx >> 9) & 1;
    int token = idx >> 10;
    int t     = token % TLEN;

    float inv = expf(-(float)d * (9.210340371976184f / 32.0f));
    float f   = (float)t * inv;
    float c = cosf(f), s = sinf(f);

    size_t base = (size_t)token * (3 * DIM) + sec * DIM + h * DH + d;
    float v1 = g_qkv[base];
    float v2 = g_qkv[base + 32];
    g_qkv[base]      = v1 * c - v2 * s;
    g_qkv[base + 32] = v2 * c + v1 * s;
}

// ---------------- 4) windowed causal attention (identical to R1) ----------
__global__ __launch_bounds__(256)
void attn_kernel() {
    const int t0 = blockIdx.x * 32;
    const int bh = blockIdx.y;
    const int b = bh / HEADS, h = bh % HEADS;

    __shared__ float Qs[32][64];
    __shared__ float Ks[64][65];
    __shared__ float Vs[64][65];

    const int tid = threadIdx.x;

    for (int i = tid; i < 32 * 64; i += 256) {
        int q = i >> 6, d = i & 63;
        Qs[q][d] = g_qkv[((size_t)(b * TLEN + t0 + q)) * (3 * DIM) + h * DH + d];
    }
    for (int i = tid; i < 63 * 64; i += 256) {
        int rr = i >> 6, d = i & 63;
        int kpos = t0 - 31 + rr;
        float kv = 0.f, vv = 0.f;
        if (kpos >= 0) {
            size_t off = ((size_t)(b * TLEN + kpos)) * (3 * DIM) + h * DH + d;
            kv = g_qkv[off + DIM];
            vv = g_qkv[off + 2 * DIM];
        }
        Ks[rr][d] = kv;
        Vs[rr][d] = vv;
    }
    __syncthreads();

    const int warp = tid >> 5, lane = tid & 31;
    #pragma unroll
    for (int j = 0; j < 4; j++) {
        const int ql   = warp * 4 + j;
        const int qpos = t0 + ql;
        const int rr   = ql + lane;
        const int kpos = qpos - 31 + lane;
        const bool valid = (kpos >= 0);

        float s = 0.f;
        #pragma unroll
        for (int d = 0; d < 64; d++) s = fmaf(Qs[ql][d], Ks[rr][d], s);
        s *= 0.125f;
        s = valid ? s : -INFINITY;

        float m = s;
        #pragma unroll
        for (int o = 16; o; o >>= 1) m = fmaxf(m, __shfl_xor_sync(0xffffffffu, m, o));
        float p = valid ? expf(s - m) : 0.f;
        float sum = p;
        #pragma unroll
        for (int o = 16; o; o >>= 1) sum += __shfl_xor_sync(0xffffffffu, sum, o);
        p /= sum;

        float o0 = 0.f, o1 = 0.f;
        #pragma unroll
        for (int jj = 0; jj < 32; jj++) {
            float pj = __shfl_sync(0xffffffffu, p, jj);
            int rj = ql + jj;
            o0 = fmaf(pj, Vs[rj][2 * lane],     o0);
            o1 = fmaf(pj, Vs[rj][2 * lane + 1], o1);
        }
        size_t oo = ((size_t)(b * TLEN + qpos)) * DIM + h * DH + 2 * lane;
        g_att[oo]     = o0;
        g_att[oo + 1] = o1;
    }
}

// ---------------- 6) transpose + residual (identical to R1) ---------------
__global__ void add_transpose_kernel(const float* __restrict__ x,
                                     float* __restrict__ out) {
    const int b  = blockIdx.z;
    const int t0 = blockIdx.x * 32, c0 = blockIdx.y * 32;
    const int tx = threadIdx.x, ty = threadIdx.y;
    __shared__ float tile[32][33];
    #pragma unroll
    for (int k = 0; k < 4; k++) {
        int tl = ty + 8 * k;
        tile[tl][tx] = g_proj[((size_t)(b * TLEN + t0 + tl)) * DIM + c0 + tx];
    }
    __syncthreads();
    #pragma unroll
    for (int k = 0; k < 4; k++) {
        int cl = ty + 8 * k;
        size_t idx = ((size_t)b * DIM + c0 + cl) * TLEN + t0 + tx;
        out[idx] = tile[tx][cl] + x[idx];
    }
}

// ---------------- launch ---------------------------------------------------
extern "C" void kernel_launch(void* const* d_in, const int* in_sizes, int n_in,
                              void* d_out, int out_size) {
    const float* x     = (const float*)d_in[0];
    const float* ln_w  = (const float*)d_in[1];
    const float* ln_b  = (const float*)d_in[2];
    const float* w_qkv = (const float*)d_in[3];
    const float* w_out = (const float*)d_in[4];
    float* out = (float*)d_out;

    // 1) LayerNorm + transpose to [tok, DIM] fp32
    ln_transpose_kernel<<<dim3(TLEN / 32, BATCH), dim3(32, 8)>>>(x, ln_w, ln_b);

    // 2) QKV GEMM (bf16x3, in-register split): [4096,1024]x[1024,3072]
    sgemm_tc_kernel<<<dim3((3 * DIM) / 64, NTOK / 128), 256>>>(0, w_qkv, 3 * DIM);

    // 3) RoPE on q,k
    {
        int total = NTOK * 1024;
        rope_kernel<<<(total + 255) / 256, 256>>>();
    }

    // 4) windowed attention
    attn_kernel<<<dim3(TLEN / 32, BATCH * HEADS), 256>>>();

    // 5) output projection: [4096,1024]x[1024,1024]
    sgemm_tc_kernel<<<dim3(DIM / 64, NTOK / 128), 256>>>(1, w_out, DIM);

    // 6) transpose + residual
    add_transpose_kernel<<<dim3(TLEN / 32, DIM / 32, BATCH), dim3(32, 8)>>>(x, out);
}

// round 9
// speedup vs baseline: 1.9264x; 1.1077x over previous
#include <cuda_runtime.h>
#include <cuda_bf16.h>
#include <cstdint>
#include <math.h>

#define BATCH 2
#define TLEN 2048
#define DIM 1024
#define HEADS 16
#define DH 64
#define WINDOW 32
#define NTOK (BATCH * TLEN)
#define LN_EPS 1e-5f

// ---------------- scratch (device globals; same 96 MB set as R8) ----------
__device__ float g_h[(size_t)NTOK * DIM];          // LN output, [tok, DIM]
__device__ float g_qkv[(size_t)NTOK * 3 * DIM];    // [tok, 3*DIM]
__device__ float g_att[(size_t)NTOK * DIM];        // attention output, [tok, DIM]
__device__ float g_proj[(size_t)NTOK * DIM];       // out-proj, [tok, DIM]

// ---------------- 1) LayerNorm + transpose [B,C,T] -> [tok,C] -------------
__global__ void ln_transpose_kernel(const float* __restrict__ x,
                                    const float* __restrict__ w,
                                    const float* __restrict__ bias) {
    const int b  = blockIdx.y;
    const int t0 = blockIdx.x * 32;
    const int tx = threadIdx.x, ty = threadIdx.y;
    const float* xb = x + (size_t)b * DIM * TLEN;

    float s = 0.f, ss = 0.f;
    for (int c = ty; c < DIM; c += 8) {
        float v = xb[(size_t)c * TLEN + t0 + tx];
        s += v; ss += v * v;
    }
    __shared__ float rs[8][32], rq[8][32];
    rs[ty][tx] = s; rq[ty][tx] = ss;
    __syncthreads();
    __shared__ float mu[32], rstd[32];
    if (ty == 0) {
        float a = 0.f, q = 0.f;
        #pragma unroll
        for (int i = 0; i < 8; i++) { a += rs[i][tx]; q += rq[i][tx]; }
        float m   = a / (float)DIM;
        float var = q / (float)DIM - m * m;
        mu[tx]   = m;
        rstd[tx] = rsqrtf(var + LN_EPS);
    }
    __syncthreads();

    __shared__ float tile[32][33];
    for (int c0 = 0; c0 < DIM; c0 += 32) {
        #pragma unroll
        for (int k = 0; k < 4; k++) {
            int cl = ty + 8 * k;
            tile[cl][tx] = xb[(size_t)(c0 + cl) * TLEN + t0 + tx];
        }
        __syncthreads();
        #pragma unroll
        for (int k = 0; k < 4; k++) {
            int tl = ty + 8 * k;
            int c  = c0 + tx;
            float v = (tile[tx][tl] - mu[tl]) * rstd[tl] * w[c] + bias[c];
            g_h[((size_t)b * TLEN + t0 + tl) * DIM + c] = v;
        }
        __syncthreads();
    }
}

// ---------------- 2/5) bf16x3 tensor-core GEMM, pipelined -----------------
// C[M,N] = A[M,K] * B[K,N], fp32 in/out, bf16x3 via in-register split.
// CTA tile 128x64xk32, 8 warps (4m x 2n), warp tile 32x32.
// Register-prefetch pipelining: fetch tile kt+1 while computing kt.
#define ASTRIDE 36   // fp32 A smem row stride (128 rows x 32 cols)
#define BSTRIDE 68   // fp32 B smem row stride (32 rows x 64 cols)

#define MMA16816(d, a0, a1, a2, a3, b0, b1)                                   \
    asm volatile("mma.sync.aligned.m16n8k16.row.col.f32.bf16.bf16.f32 "      \
                 "{%0,%1,%2,%3}, {%4,%5,%6,%7}, {%8,%9}, {%0,%1,%2,%3};"     \
                 : "+f"(d[0]), "+f"(d[1]), "+f"(d[2]), "+f"(d[3])             \
                 : "r"(a0), "r"(a1), "r"(a2), "r"(a3), "r"(b0), "r"(b1))

__device__ __forceinline__ void split2(float fx, float fy,
                                       uint32_t& hi, uint32_t& lo) {
    __nv_bfloat162 h = __floats2bfloat162_rn(fx, fy);
    float2 hf = __bfloat1622float2(h);
    __nv_bfloat162 l = __floats2bfloat162_rn(fx - hf.x, fy - hf.y);
    hi = *(uint32_t*)&h;
    lo = *(uint32_t*)&l;
}

__global__ __launch_bounds__(256)
void sgemm_tc_kernel(int which, const float* __restrict__ Bm, int N) {
    const float* __restrict__ A = (which == 0) ? g_h : g_att;
    float* __restrict__ C = (which == 0) ? g_qkv : g_proj;
    const int K = DIM;

    __shared__ float sA[128 * ASTRIDE];   // 18432 B
    __shared__ float sB[32 * BSTRIDE];    //  8704 B

    const int tid  = threadIdx.x;
    const int warp = tid >> 5, lane = tid & 31;
    const int wm0 = (warp & 3) * 32;
    const int wn0 = (warp >> 2) * 32;
    const int m0 = blockIdx.y * 128;
    const int n0 = blockIdx.x * 64;

    float acc[2][4][4];
    #pragma unroll
    for (int i = 0; i < 2; i++)
        #pragma unroll
        for (int j = 0; j < 4; j++)
            #pragma unroll
            for (int k = 0; k < 4; k++) acc[i][j][k] = 0.f;

    const int r  = lane >> 2;
    const int c2 = (lane & 3) * 2;

    // loader mapping (A: 4 float4/thread, B: 2 float4/thread)
    const int ar = tid >> 3;             // base row 0..31 (i adds 32*i)
    const int ac = (tid & 7) * 4;        // col 0..28
    const int br = tid >> 4;             // base row 0..15 (i adds 16*i)
    const int bc = (tid & 15) * 4;       // col 0..60

    float4 pa[4], pb[2];

    #define FETCH(kt)                                                          \
    do {                                                                       \
        int kb = (kt) * 32;                                                    \
        _Pragma("unroll")                                                      \
        for (int i = 0; i < 4; i++)                                            \
            pa[i] = *(const float4*)&A[(size_t)(m0 + ar + 32 * i) * K + kb + ac]; \
        _Pragma("unroll")                                                      \
        for (int i = 0; i < 2; i++)                                            \
            pb[i] = *(const float4*)&Bm[(size_t)(kb + br + 16 * i) * N + n0 + bc]; \
    } while (0)

    #define STORE()                                                            \
    do {                                                                       \
        _Pragma("unroll")                                                      \
        for (int i = 0; i < 4; i++)                                            \
            *(float4*)&sA[(ar + 32 * i) * ASTRIDE + ac] = pa[i];               \
        _Pragma("unroll")                                                      \
        for (int i = 0; i < 2; i++)                                            \
            *(float4*)&sB[(br + 16 * i) * BSTRIDE + bc] = pb[i];               \
    } while (0)

    const int ntiles = K / 32;
    FETCH(0);

    for (int kt = 0; kt < ntiles; kt++) {
        STORE();
        __syncthreads();
        if (kt + 1 < ntiles) FETCH(kt + 1);   // overlap with compute below

        #pragma unroll
        for (int ks = 0; ks < 2; ks++) {
            const int kc = ks * 16 + c2;
            uint32_t bh[4][2], bl[4][2];
            #pragma unroll
            for (int nt = 0; nt < 4; nt++) {
                int n = wn0 + nt * 8 + r;
                split2(sB[kc * BSTRIDE + n],       sB[(kc + 1) * BSTRIDE + n],
                       bh[nt][0], bl[nt][0]);
                split2(sB[(kc + 8) * BSTRIDE + n], sB[(kc + 9) * BSTRIDE + n],
                       bh[nt][1], bl[nt][1]);
            }
            #pragma unroll
            for (int mt = 0; mt < 2; mt++) {
                int row = wm0 + mt * 16 + r;
                float2 f0 = *(const float2*)&sA[row * ASTRIDE + kc];
                float2 f1 = *(const float2*)&sA[(row + 8) * ASTRIDE + kc];
                float2 f2 = *(const float2*)&sA[row * ASTRIDE + kc + 8];
                float2 f3 = *(const float2*)&sA[(row + 8) * ASTRIDE + kc + 8];
                uint32_t ah0, ah1, ah2, ah3, al0, al1, al2, al3;
                split2(f0.x, f0.y, ah0, al0);
                split2(f1.x, f1.y, ah1, al1);
                split2(f2.x, f2.y, ah2, al2);
                split2(f3.x, f3.y, ah3, al3);
                #pragma unroll
                for (int nt = 0; nt < 4; nt++) {
                    MMA16816(acc[mt][nt], ah0, ah1, ah2, ah3, bh[nt][0], bh[nt][1]);
                    MMA16816(acc[mt][nt], ah0, ah1, ah2, ah3, bl[nt][0], bl[nt][1]);
                    MMA16816(acc[mt][nt], al0, al1, al2, al3, bh[nt][0], bh[nt][1]);
                }
            }
        }
        __syncthreads();
    }
    #undef FETCH
    #undef STORE

    #pragma unroll
    for (int mt = 0; mt < 2; mt++)
        #pragma unroll
        for (int nt = 0; nt < 4; nt++) {
            int row = m0 + wm0 + mt * 16 + r;
            int col = n0 + wn0 + nt * 8 + c2;
            float2 v0 = make_float2(acc[mt][nt][0], acc[mt][nt][1]);
            float2 v1 = make_float2(acc[mt][nt][2], acc[mt][nt][3]);
            *(float2*)&C[(size_t)row * N + col]       = v0;
            *(float2*)&C[(size_t)(row + 8) * N + col] = v1;
        }
}

// ---------------- 3) RoPE in-place on q,k sections of g_qkv ---------------
__global__ void rope_kernel() {
    int idx = blockIdx.x * blockDim.x + threadIdx.x;
    if (idx >= NTOK * 1024) return;
    int d     = idx & 31;
    int h     = (idx >> 5) & 15;
    int sec   = (idx >> 9) & 1;
    int token = idx >> 10;
    int t     = token % TLEN;

    float inv = expf(-(float)d * (9.210340371976184f / 32.0f));
    float f   = (float)t * inv;
    float c = cosf(f), s = sinf(f);

    size_t base = (size_t)token * (3 * DIM) + sec * DIM + h * DH + d;
    float v1 = g_qkv[base];
    float v2 = g_qkv[base + 32];
    g_qkv[base]      = v1 * c - v2 * s;
    g_qkv[base + 32] = v2 * c + v1 * s;
}

// ---------------- 4) windowed causal attention -----------------------------
__global__ __launch_bounds__(256)
void attn_kernel() {
    const int t0 = blockIdx.x * 32;
    const int bh = blockIdx.y;
    const int b = bh / HEADS, h = bh % HEADS;

    __shared__ float Qs[32][64];
    __shared__ float Ks[64][65];
    __shared__ float Vs[64][65];

    const int tid = threadIdx.x;

    for (int i = tid; i < 32 * 64; i += 256) {
        int q = i >> 6, d = i & 63;
        Qs[q][d] = g_qkv[((size_t)(b * TLEN + t0 + q)) * (3 * DIM) + h * DH + d];
    }
    for (int i = tid; i < 63 * 64; i += 256) {
        int rr = i >> 6, d = i & 63;
        int kpos = t0 - 31 + rr;
        float kv = 0.f, vv = 0.f;
        if (kpos >= 0) {
            size_t off = ((size_t)(b * TLEN + kpos)) * (3 * DIM) + h * DH + d;
            kv = g_qkv[off + DIM];
            vv = g_qkv[off + 2 * DIM];
        }
        Ks[rr][d] = kv;
        Vs[rr][d] = vv;
    }
    __syncthreads();

    const int warp = tid >> 5, lane = tid & 31;
    #pragma unroll
    for (int j = 0; j < 4; j++) {
        const int ql   = warp * 4 + j;
        const int qpos = t0 + ql;
        const int rr   = ql + lane;
        const int kpos = qpos - 31 + lane;
        const bool valid = (kpos >= 0);

        float s = 0.f;
        #pragma unroll
        for (int d = 0; d < 64; d++) s = fmaf(Qs[ql][d], Ks[rr][d], s);
        s *= 0.125f;
        s = valid ? s : -INFINITY;

        float m = s;
        #pragma unroll
        for (int o = 16; o; o >>= 1) m = fmaxf(m, __shfl_xor_sync(0xffffffffu, m, o));
        float p = valid ? expf(s - m) : 0.f;
        float sum = p;
        #pragma unroll
        for (int o = 16; o; o >>= 1) sum += __shfl_xor_sync(0xffffffffu, sum, o);
        p /= sum;

        float o0 = 0.f, o1 = 0.f;
        #pragma unroll
        for (int jj = 0; jj < 32; jj++) {
            float pj = __shfl_sync(0xffffffffu, p, jj);
            int rj = ql + jj;
            o0 = fmaf(pj, Vs[rj][2 * lane],     o0);
            o1 = fmaf(pj, Vs[rj][2 * lane + 1], o1);
        }
        size_t oo = ((size_t)(b * TLEN + qpos)) * DIM + h * DH + 2 * lane;
        g_att[oo]     = o0;
        g_att[oo + 1] = o1;
    }
}

// ---------------- 6) transpose + residual ----------------------------------
__global__ void add_transpose_kernel(const float* __restrict__ x,
                                     float* __restrict__ out) {
    const int b  = blockIdx.z;
    const int t0 = blockIdx.x * 32, c0 = blockIdx.y * 32;
    const int tx = threadIdx.x, ty = threadIdx.y;
    __shared__ float tile[32][33];
    #pragma unroll
    for (int k = 0; k < 4; k++) {
        int tl = ty + 8 * k;
        tile[tl][tx] = g_proj[((size_t)(b * TLEN + t0 + tl)) * DIM + c0 + tx];
    }
    __syncthreads();
    #pragma unroll
    for (int k = 0; k < 4; k++) {
        int cl = ty + 8 * k;
        size_t idx = ((size_t)b * DIM + c0 + cl) * TLEN + t0 + tx;
        out[idx] = tile[tx][cl] + x[idx];
    }
}

// ---------------- launch ---------------------------------------------------
extern "C" void kernel_launch(void* const* d_in, const int* in_sizes, int n_in,
                              void* d_out, int out_size) {
    const float* x     = (const float*)d_in[0];
    const float* ln_w  = (const float*)d_in[1];
    const float* ln_b  = (const float*)d_in[2];
    const float* w_qkv = (const float*)d_in[3];
    const float* w_out = (const float*)d_in[4];
    float* out = (float*)d_out;

    ln_transpose_kernel<<<dim3(TLEN / 32, BATCH), dim3(32, 8)>>>(x, ln_w, ln_b);

    // QKV GEMM: [4096,1024]x[1024,3072]
    sgemm_tc_kernel<<<dim3((3 * DIM) / 64, NTOK / 128), 256>>>(0, w_qkv, 3 * DIM);

    {
        int total = NTOK * 1024;
        rope_kernel<<<(total + 255) / 256, 256>>>();
    }

    attn_kernel<<<dim3(TLEN / 32, BATCH * HEADS), 256>>>();

    // out projection: [4096,1024]x[1024,1024]
    sgemm_tc_kernel<<<dim3(DIM / 64, NTOK / 128), 256>>>(1, w_out, DIM);

    add_transpose_kernel<<<dim3(TLEN / 32, DIM / 32, BATCH), dim3(32, 8)>>>(x, out);
}